// round 7
// baseline (speedup 1.0000x reference)
#include <cuda_runtime.h>
#include <cuda_bf16.h>
#include <cuda_fp16.h>
#include <cstdint>

// Problem constants (fixed by the dataset)
#define KDIM 256      // IN_DIM
#define UDIM 128      // UNITS
#define MAX_NODES 100000
#define MAX_EDGES 3200000
#define SCAN_TILE 1024
#define MAX_SCAN_BLOCKS 1024

// ---------------- device scratch (static globals: no runtime alloc) ----------
__device__ __half             g_h[(size_t)MAX_NODES * UDIM];   // 25.6 MB (fp16)
__device__ int                g_cnt[MAX_NODES];                // zero-init; self-zeroing
__device__ int                g_off[MAX_NODES + 1];
__device__ int                g_cur[MAX_NODES];
__device__ int                g_bsum[MAX_SCAN_BLOCKS];
__device__ unsigned long long g_cv[MAX_EDGES];                 // packed (col, val)
// W split into bf16 hi/lo, transposed to K-major: [UDIM][KDIM]
__device__ __nv_bfloat16      g_bhi[UDIM * KDIM];
__device__ __nv_bfloat16      g_blo[UDIM * KDIM];

// ---------------- small helpers ----------------------------------------------
__device__ __forceinline__ uint32_t smem_u32(const void* p) {
    uint32_t a;
    asm("{ .reg .u64 t; cvta.to.shared.u64 t, %1; cvt.u32.u64 %0, t; }"
        : "=r"(a) : "l"(p));
    return a;
}

__device__ __forceinline__ void ldmatrix_x4(uint32_t& r0, uint32_t& r1,
                                            uint32_t& r2, uint32_t& r3,
                                            uint32_t addr)
{
    asm volatile("ldmatrix.sync.aligned.m8n8.x4.shared.b16 {%0,%1,%2,%3}, [%4];"
                 : "=r"(r0), "=r"(r1), "=r"(r2), "=r"(r3) : "r"(addr));
}

__device__ __forceinline__ void mma_bf16(float* d, const uint32_t* a,
                                         uint32_t b0, uint32_t b1)
{
    asm volatile(
        "mma.sync.aligned.m16n8k16.row.col.f32.bf16.bf16.f32 "
        "{%0,%1,%2,%3}, {%4,%5,%6,%7}, {%8,%9}, {%0,%1,%2,%3};"
        : "+f"(d[0]), "+f"(d[1]), "+f"(d[2]), "+f"(d[3])
        : "r"(a[0]), "r"(a[1]), "r"(a[2]), "r"(a[3]), "r"(b0), "r"(b1));
}

// ============================================================================
// 0) W prep: split + transpose W[256][128] -> g_bhi/g_blo [128][256] K-major
// ============================================================================
__global__ void wprep_kernel(const float* __restrict__ W)
{
    int i = blockIdx.x * blockDim.x + threadIdx.x;
    if (i < KDIM * UDIM) {
        int k = i / UDIM, n = i % UDIM;
        float w = W[i];
        __nv_bfloat16 hi = __float2bfloat16(w);
        float lo = w - __bfloat162float(hi);
        g_bhi[n * KDIM + k] = hi;
        g_blo[n * KDIM + k] = __float2bfloat16(lo);
    }
}

// ============================================================================
// 1) FUSED: GEMM (blocks [0, gemm_nb)) + edge histogram (blocks [gemm_nb, ..))
//    GEMM: mma.sync bf16 3-term hi/lo split, fp32 accum, fp16 h output
//    BM=128, BN=128, BK=32, 256 threads (8 warps), warp tile 32x64
// ============================================================================
#define PITCH 80
#define HIST_CHUNK 256

__global__ __launch_bounds__(256) void gemm_hist_kernel(
    const float* __restrict__ X, const int* __restrict__ rows,
    int M, int E, int gemm_nb)
{
    __shared__ __align__(16) char sA_hi[128 * PITCH];
    __shared__ __align__(16) char sA_lo[128 * PITCH];
    __shared__ __align__(16) char sB_hi[128 * PITCH];
    __shared__ __align__(16) char sB_lo[128 * PITCH];

    const int tid = threadIdx.x;

    if ((int)blockIdx.x >= gemm_nb) {
        // ---------------- histogram role ----------------
        int i = (blockIdx.x - gemm_nb) * HIST_CHUNK + tid;
        if (i < E) atomicAdd(&g_cnt[rows[i]], 1);
        return;
    }

    // ---------------- GEMM role ----------------
    const int wid  = tid >> 5;
    const int lane = tid & 31;
    const int warpM = wid & 3;        // 4 groups of 32 rows
    const int warpN = wid >> 2;       // 2 groups of 64 cols
    const int block_row = blockIdx.x * 128;

    float acc[2][8][4];
#pragma unroll
    for (int mg = 0; mg < 2; mg++)
#pragma unroll
        for (int ng = 0; ng < 8; ng++)
#pragma unroll
            for (int q = 0; q < 4; q++) acc[mg][ng][q] = 0.0f;

    const int matIdx = lane >> 3;
    const int rowInMat = lane & 7;
    const int a_roff = rowInMat + (matIdx & 1) * 8;
    const int a_koff = (matIdx >> 1) * 8;
    const int b_noff = (matIdx >> 1) * 8 + rowInMat;
    const int b_koff = (matIdx & 1) * 8;

    const uint32_t sAhi = smem_u32(sA_hi);
    const uint32_t sAlo = smem_u32(sA_lo);
    const uint32_t sBhi = smem_u32(sB_hi);
    const uint32_t sBlo = smem_u32(sB_lo);

    const int ld_row  = tid >> 1;     // 0..127
    const int ld_half = tid & 1;      // 0/1 -> 16 elements each

#pragma unroll 1
    for (int kc = 0; kc < KDIM; kc += 32) {
        // ---- A: load 16 fp32, split hi/lo, store bf16
        {
            int grow = block_row + ld_row;
            float f[16];
            if (grow < M) {
                const float4* xp = (const float4*)(X + (size_t)grow * KDIM + kc + ld_half * 16);
#pragma unroll
                for (int q = 0; q < 4; q++) {
                    float4 v = xp[q];
                    f[q * 4 + 0] = v.x; f[q * 4 + 1] = v.y;
                    f[q * 4 + 2] = v.z; f[q * 4 + 3] = v.w;
                }
            } else {
#pragma unroll
                for (int q = 0; q < 16; q++) f[q] = 0.0f;
            }
            union { __nv_bfloat16 b[16]; uint4 u[2]; } hi, lo;
#pragma unroll
            for (int q = 0; q < 16; q++) {
                __nv_bfloat16 h = __float2bfloat16(f[q]);
                hi.b[q] = h;
                lo.b[q] = __float2bfloat16(f[q] - __bfloat162float(h));
            }
            char* pa = sA_hi + ld_row * PITCH + ld_half * 32;
            char* pl = sA_lo + ld_row * PITCH + ld_half * 32;
            *(uint4*)(pa)      = hi.u[0];
            *(uint4*)(pa + 16) = hi.u[1];
            *(uint4*)(pl)      = lo.u[0];
            *(uint4*)(pl + 16) = lo.u[1];
        }
        // ---- B: copy pre-split bf16 (K-major)
        {
            const uint4* bh = (const uint4*)(g_bhi + ld_row * KDIM + kc + ld_half * 16);
            const uint4* bl = (const uint4*)(g_blo + ld_row * KDIM + kc + ld_half * 16);
            char* ph = sB_hi + ld_row * PITCH + ld_half * 32;
            char* pl = sB_lo + ld_row * PITCH + ld_half * 32;
            *(uint4*)(ph)      = bh[0];
            *(uint4*)(ph + 16) = bh[1];
            *(uint4*)(pl)      = bl[0];
            *(uint4*)(pl + 16) = bl[1];
        }
        __syncthreads();

#pragma unroll
        for (int ks = 0; ks < 2; ks++) {
            const int k0 = ks * 16;
            uint32_t ah[2][4], al[2][4];
#pragma unroll
            for (int mg = 0; mg < 2; mg++) {
                int row = warpM * 32 + mg * 16 + a_roff;
                uint32_t off = (uint32_t)(row * PITCH + (k0 + a_koff) * 2);
                ldmatrix_x4(ah[mg][0], ah[mg][1], ah[mg][2], ah[mg][3], sAhi + off);
                ldmatrix_x4(al[mg][0], al[mg][1], al[mg][2], al[mg][3], sAlo + off);
            }
            uint32_t bh[4][4], bl[4][4];
#pragma unroll
            for (int g = 0; g < 4; g++) {
                int n = warpN * 64 + g * 16 + b_noff;
                uint32_t off = (uint32_t)(n * PITCH + (k0 + b_koff) * 2);
                ldmatrix_x4(bh[g][0], bh[g][1], bh[g][2], bh[g][3], sBhi + off);
                ldmatrix_x4(bl[g][0], bl[g][1], bl[g][2], bl[g][3], sBlo + off);
            }
#pragma unroll
            for (int mg = 0; mg < 2; mg++) {
#pragma unroll
                for (int ng = 0; ng < 8; ng++) {
                    int g = ng >> 1, s = (ng & 1) * 2;
                    mma_bf16(acc[mg][ng], ah[mg], bh[g][s], bh[g][s + 1]); // hi*hi
                    mma_bf16(acc[mg][ng], al[mg], bh[g][s], bh[g][s + 1]); // lo*hi
                    mma_bf16(acc[mg][ng], ah[mg], bl[g][s], bl[g][s + 1]); // hi*lo
                }
            }
        }
        __syncthreads();
    }

    // ---- epilogue: write h as fp16
    const int qrow = lane >> 2;          // 0..7
    const int qcol = (lane & 3) * 2;     // 0,2,4,6
#pragma unroll
    for (int mg = 0; mg < 2; mg++) {
#pragma unroll
        for (int ng = 0; ng < 8; ng++) {
            int col = warpN * 64 + ng * 8 + qcol;
            int r0 = block_row + warpM * 32 + mg * 16 + qrow;
            if (r0 < M)
                *(__half2*)(g_h + (size_t)r0 * UDIM + col) =
                    __floats2half2_rn(acc[mg][ng][0], acc[mg][ng][1]);
            int r1 = r0 + 8;
            if (r1 < M)
                *(__half2*)(g_h + (size_t)r1 * UDIM + col) =
                    __floats2half2_rn(acc[mg][ng][2], acc[mg][ng][3]);
        }
    }
}

// ============================================================================
// 2) CSR build: scan (3 phases) + scatter.  scan_final self-zeroes g_cnt.
// ============================================================================
__global__ __launch_bounds__(SCAN_TILE) void scan_bsum_kernel(int n)
{
    __shared__ int wsum[SCAN_TILE / 32];
    const int tid  = threadIdx.x;
    const int lane = tid & 31;
    const int wid  = tid >> 5;
    int i = blockIdx.x * SCAN_TILE + tid;
    int v = (i < n) ? g_cnt[i] : 0;

#pragma unroll
    for (int off = 16; off > 0; off >>= 1)
        v += __shfl_down_sync(0xffffffffu, v, off);
    if (lane == 0) wsum[wid] = v;
    __syncthreads();
    if (wid == 0) {
        int w = (lane < SCAN_TILE / 32) ? wsum[lane] : 0;
#pragma unroll
        for (int off = 16; off > 0; off >>= 1)
            w += __shfl_down_sync(0xffffffffu, w, off);
        if (lane == 0) g_bsum[blockIdx.x] = w;
    }
}

__global__ __launch_bounds__(1024) void scan_bases_kernel(int nb)
{
    __shared__ int wsum[32];
    const int tid  = threadIdx.x;
    const int lane = tid & 31;
    const int wid  = tid >> 5;
    int v = (tid < nb) ? g_bsum[tid] : 0;

    int s = v;
#pragma unroll
    for (int off = 1; off < 32; off <<= 1) {
        int t = __shfl_up_sync(0xffffffffu, s, off);
        if (lane >= off) s += t;
    }
    if (lane == 31) wsum[wid] = s;
    __syncthreads();
    if (wid == 0) {
        int w = wsum[lane];
#pragma unroll
        for (int off = 1; off < 32; off <<= 1) {
            int t = __shfl_up_sync(0xffffffffu, w, off);
            if (lane >= off) w += t;
        }
        wsum[lane] = w;
    }
    __syncthreads();
    int wp = (wid > 0) ? wsum[wid - 1] : 0;
    if (tid < nb) g_bsum[tid] = wp + s - v;
}

__global__ __launch_bounds__(SCAN_TILE) void scan_final_kernel(int n)
{
    __shared__ int wsum[SCAN_TILE / 32];
    const int tid  = threadIdx.x;
    const int lane = tid & 31;
    const int wid  = tid >> 5;
    int i = blockIdx.x * SCAN_TILE + tid;
    int v = (i < n) ? g_cnt[i] : 0;

    int s = v;
#pragma unroll
    for (int off = 1; off < 32; off <<= 1) {
        int t = __shfl_up_sync(0xffffffffu, s, off);
        if (lane >= off) s += t;
    }
    if (lane == 31) wsum[wid] = s;
    __syncthreads();
    if (wid == 0) {
        int w = wsum[lane];
#pragma unroll
        for (int off = 1; off < 32; off <<= 1) {
            int t = __shfl_up_sync(0xffffffffu, w, off);
            if (lane >= off) w += t;
        }
        wsum[lane] = w;
    }
    __syncthreads();
    int wp = (wid > 0) ? wsum[wid - 1] : 0;
    int incl = g_bsum[blockIdx.x] + wp + s;
    if (i < n) {
        g_off[i + 1] = incl;
        g_cur[i]     = incl - v;
        g_cnt[i]     = 0;        // self-zero for the next graph replay
    }
    if (i == 0) g_off[0] = 0;
}

__global__ void scatter_kernel(const int* __restrict__ rows,
                               const int* __restrict__ cols,
                               const float* __restrict__ vals, int E)
{
    int i = blockIdx.x * blockDim.x + threadIdx.x;
    if (i < E) {
        int r = rows[i];
        int p = atomicAdd(&g_cur[r], 1);
        unsigned long long packed =
            (unsigned long long)(unsigned)cols[i] |
            ((unsigned long long)__float_as_uint(vals[i]) << 32);
        g_cv[p] = packed;
    }
}

// ============================================================================
// 3) Segment reduce: one warp per output row, fp16 h gathers, fp32 accum
// ============================================================================
__global__ void reduce_kernel(float* __restrict__ out, int M)
{
    int warp = (blockIdx.x * blockDim.x + threadIdx.x) >> 5;
    int lane = threadIdx.x & 31;
    if (warp >= M) return;

    int s = g_off[warp];
    int e = g_off[warp + 1];

    float4 acc = make_float4(0.f, 0.f, 0.f, 0.f);
    int i = s;
    for (; i + 3 < e; i += 4) {
        unsigned long long p0 = __ldg(&g_cv[i]);
        unsigned long long p1 = __ldg(&g_cv[i + 1]);
        unsigned long long p2 = __ldg(&g_cv[i + 2]);
        unsigned long long p3 = __ldg(&g_cv[i + 3]);
        int c0 = (int)(unsigned)(p0 & 0xffffffffu);
        int c1 = (int)(unsigned)(p1 & 0xffffffffu);
        int c2 = (int)(unsigned)(p2 & 0xffffffffu);
        int c3 = (int)(unsigned)(p3 & 0xffffffffu);
        float v0 = __uint_as_float((unsigned)(p0 >> 32));
        float v1 = __uint_as_float((unsigned)(p1 >> 32));
        float v2 = __uint_as_float((unsigned)(p2 >> 32));
        float v3 = __uint_as_float((unsigned)(p3 >> 32));
        uint2 u0 = ((const uint2*)(g_h + (size_t)c0 * UDIM))[lane];
        uint2 u1 = ((const uint2*)(g_h + (size_t)c1 * UDIM))[lane];
        uint2 u2 = ((const uint2*)(g_h + (size_t)c2 * UDIM))[lane];
        uint2 u3 = ((const uint2*)(g_h + (size_t)c3 * UDIM))[lane];
        float2 a0 = __half22float2(*(__half2*)&u0.x);
        float2 b0 = __half22float2(*(__half2*)&u0.y);
        float2 a1 = __half22float2(*(__half2*)&u1.x);
        float2 b1 = __half22float2(*(__half2*)&u1.y);
        float2 a2 = __half22float2(*(__half2*)&u2.x);
        float2 b2 = __half22float2(*(__half2*)&u2.y);
        float2 a3 = __half22float2(*(__half2*)&u3.x);
        float2 b3 = __half22float2(*(__half2*)&u3.y);
        acc.x = fmaf(v0, a0.x, acc.x); acc.y = fmaf(v0, a0.y, acc.y);
        acc.z = fmaf(v0, b0.x, acc.z); acc.w = fmaf(v0, b0.y, acc.w);
        acc.x = fmaf(v1, a1.x, acc.x); acc.y = fmaf(v1, a1.y, acc.y);
        acc.z = fmaf(v1, b1.x, acc.z); acc.w = fmaf(v1, b1.y, acc.w);
        acc.x = fmaf(v2, a2.x, acc.x); acc.y = fmaf(v2, a2.y, acc.y);
        acc.z = fmaf(v2, b2.x, acc.z); acc.w = fmaf(v2, b2.y, acc.w);
        acc.x = fmaf(v3, a3.x, acc.x); acc.y = fmaf(v3, a3.y, acc.y);
        acc.z = fmaf(v3, b3.x, acc.z); acc.w = fmaf(v3, b3.y, acc.w);
    }
    for (; i < e; i++) {
        unsigned long long p0 = __ldg(&g_cv[i]);
        int c0 = (int)(unsigned)(p0 & 0xffffffffu);
        float v0 = __uint_as_float((unsigned)(p0 >> 32));
        uint2 u0 = ((const uint2*)(g_h + (size_t)c0 * UDIM))[lane];
        float2 a0 = __half22float2(*(__half2*)&u0.x);
        float2 b0 = __half22float2(*(__half2*)&u0.y);
        acc.x = fmaf(v0, a0.x, acc.x); acc.y = fmaf(v0, a0.y, acc.y);
        acc.z = fmaf(v0, b0.x, acc.z); acc.w = fmaf(v0, b0.y, acc.w);
    }

    acc.x = fmaxf(acc.x, 0.f); acc.y = fmaxf(acc.y, 0.f);
    acc.z = fmaxf(acc.z, 0.f); acc.w = fmaxf(acc.w, 0.f);

    ((float4*)(out + (size_t)warp * UDIM))[lane] = acc;
}

// ============================================================================
// launch
// ============================================================================
extern "C" void kernel_launch(void* const* d_in, const int* in_sizes, int n_in,
                              void* d_out, int out_size)
{
    const float* x      = (const float*)d_in[0];  // [M, 256]
    const float* kernel = (const float*)d_in[1];  // [256, 128]
    const int*   arows  = (const int*)d_in[2];    // [E]
    const int*   acols  = (const int*)d_in[3];    // [E]
    const float* avals  = (const float*)d_in[4];  // [E]
    float*       out    = (float*)d_out;          // [M, 128]

    const int M = in_sizes[0] / KDIM;
    const int E = in_sizes[2];
    const int nb = (M + SCAN_TILE - 1) / SCAN_TILE;

    const int gemm_nb = (M + 127) / 128;
    const int hist_nb = (E + HIST_CHUNK - 1) / HIST_CHUNK;

    // 1) W prep, then FUSED GEMM + histogram (independent work, co-scheduled)
    wprep_kernel<<<(KDIM * UDIM + 255) / 256, 256>>>(kernel);
    gemm_hist_kernel<<<gemm_nb + hist_nb, 256>>>(x, arows, M, E, gemm_nb);

    // 2) scan + scatter (scan_final self-zeroes g_cnt for the next replay)
    scan_bsum_kernel<<<nb, SCAN_TILE>>>(M);
    scan_bases_kernel<<<1, 1024>>>(nb);
    scan_final_kernel<<<nb, SCAN_TILE>>>(M);
    scatter_kernel<<<(E + 255) / 256, 256>>>(arows, acols, avals, E);

    // 3) atomic-free segment reduce + relu (fp16 gathers)
    int warps_per_block = 256 / 32;
    int blocks = (M + warps_per_block - 1) / warps_per_block;
    reduce_kernel<<<blocks, 256>>>(out, M);
}

// round 8
// speedup vs baseline: 1.1237x; 1.1237x over previous
#include <cuda_runtime.h>
#include <cuda_bf16.h>
#include <cuda_fp16.h>
#include <cstdint>

// Problem constants (fixed by the dataset)
#define KDIM 256      // IN_DIM
#define UDIM 128      // UNITS
#define MAX_NODES 100000
#define MAX_EDGES 3200000
#define SCAN_TILE 1024
#define MAX_SCAN_BLOCKS 1024

// ---------------- device scratch (static globals: no runtime alloc) ----------
__device__ __half             g_h[(size_t)MAX_NODES * UDIM];   // 25.6 MB (fp16)
__device__ int                g_cnt[MAX_NODES];                // zero-init; self-zeroing
__device__ int                g_off[MAX_NODES + 1];
__device__ int                g_cur[MAX_NODES];
__device__ int                g_bsum[MAX_SCAN_BLOCKS];
__device__ unsigned long long g_cv[MAX_EDGES];                 // packed (col, val)
// W split into bf16 hi/lo, transposed to K-major: [UDIM][KDIM]
__device__ __nv_bfloat16      g_bhi[UDIM * KDIM];
__device__ __nv_bfloat16      g_blo[UDIM * KDIM];

// ---------------- small helpers ----------------------------------------------
__device__ __forceinline__ uint32_t smem_u32(const void* p) {
    uint32_t a;
    asm("{ .reg .u64 t; cvta.to.shared.u64 t, %1; cvt.u32.u64 %0, t; }"
        : "=r"(a) : "l"(p));
    return a;
}

__device__ __forceinline__ void ldmatrix_x4(uint32_t& r0, uint32_t& r1,
                                            uint32_t& r2, uint32_t& r3,
                                            uint32_t addr)
{
    asm volatile("ldmatrix.sync.aligned.m8n8.x4.shared.b16 {%0,%1,%2,%3}, [%4];"
                 : "=r"(r0), "=r"(r1), "=r"(r2), "=r"(r3) : "r"(addr));
}

__device__ __forceinline__ void mma_bf16(float* d, const uint32_t* a,
                                         uint32_t b0, uint32_t b1)
{
    asm volatile(
        "mma.sync.aligned.m16n8k16.row.col.f32.bf16.bf16.f32 "
        "{%0,%1,%2,%3}, {%4,%5,%6,%7}, {%8,%9}, {%0,%1,%2,%3};"
        : "+f"(d[0]), "+f"(d[1]), "+f"(d[2]), "+f"(d[3])
        : "r"(a[0]), "r"(a[1]), "r"(a[2]), "r"(a[3]), "r"(b0), "r"(b1));
}

// ============================================================================
// 0) W prep: split + transpose W[256][128] -> g_bhi/g_blo [128][256] K-major
// ============================================================================
__global__ void wprep_kernel(const float* __restrict__ W)
{
    int i = blockIdx.x * blockDim.x + threadIdx.x;
    if (i < KDIM * UDIM) {
        int k = i / UDIM, n = i % UDIM;
        float w = W[i];
        __nv_bfloat16 hi = __float2bfloat16(w);
        float lo = w - __bfloat162float(hi);
        g_bhi[n * KDIM + k] = hi;
        g_blo[n * KDIM + k] = __float2bfloat16(lo);
    }
}

// ============================================================================
// 1) FUSED v2: histogram (blocks [0, HIST_BLKS), grid-stride) first,
//    then GEMM (blocks [HIST_BLKS, HIST_BLKS+gemm_nb)).
//    GEMM: mma.sync bf16 3-term hi/lo split, fp32 accum, fp16 h output
//    BM=128, BN=128, BK=32, 256 threads (8 warps), warp tile 32x64
// ============================================================================
#define PITCH 80
#define HIST_BLKS 296

__global__ __launch_bounds__(256) void gemm_hist_kernel(
    const float* __restrict__ X, const int* __restrict__ rows,
    int M, int E)
{
    __shared__ __align__(16) char sA_hi[128 * PITCH];
    __shared__ __align__(16) char sA_lo[128 * PITCH];
    __shared__ __align__(16) char sB_hi[128 * PITCH];
    __shared__ __align__(16) char sB_lo[128 * PITCH];

    const int tid = threadIdx.x;

    if ((int)blockIdx.x < HIST_BLKS) {
        // ---------------- histogram role (grid-stride, dispatched first) -----
        const int stride = HIST_BLKS * 256;
        for (int i = blockIdx.x * 256 + tid; i < E; i += stride)
            atomicAdd(&g_cnt[rows[i]], 1);
        return;
    }

    // ---------------- GEMM role ----------------
    const int wid  = tid >> 5;
    const int lane = tid & 31;
    const int warpM = wid & 3;        // 4 groups of 32 rows
    const int warpN = wid >> 2;       // 2 groups of 64 cols
    const int block_row = (blockIdx.x - HIST_BLKS) * 128;

    float acc[2][8][4];
#pragma unroll
    for (int mg = 0; mg < 2; mg++)
#pragma unroll
        for (int ng = 0; ng < 8; ng++)
#pragma unroll
            for (int q = 0; q < 4; q++) acc[mg][ng][q] = 0.0f;

    const int matIdx = lane >> 3;
    const int rowInMat = lane & 7;
    const int a_roff = rowInMat + (matIdx & 1) * 8;
    const int a_koff = (matIdx >> 1) * 8;
    const int b_noff = (matIdx >> 1) * 8 + rowInMat;
    const int b_koff = (matIdx & 1) * 8;

    const uint32_t sAhi = smem_u32(sA_hi);
    const uint32_t sAlo = smem_u32(sA_lo);
    const uint32_t sBhi = smem_u32(sB_hi);
    const uint32_t sBlo = smem_u32(sB_lo);

    const int ld_row  = tid >> 1;     // 0..127
    const int ld_half = tid & 1;      // 0/1 -> 16 elements each

#pragma unroll 1
    for (int kc = 0; kc < KDIM; kc += 32) {
        // ---- A: load 16 fp32, split hi/lo, store bf16
        {
            int grow = block_row + ld_row;
            float f[16];
            if (grow < M) {
                const float4* xp = (const float4*)(X + (size_t)grow * KDIM + kc + ld_half * 16);
#pragma unroll
                for (int q = 0; q < 4; q++) {
                    float4 v = xp[q];
                    f[q * 4 + 0] = v.x; f[q * 4 + 1] = v.y;
                    f[q * 4 + 2] = v.z; f[q * 4 + 3] = v.w;
                }
            } else {
#pragma unroll
                for (int q = 0; q < 16; q++) f[q] = 0.0f;
            }
            union { __nv_bfloat16 b[16]; uint4 u[2]; } hi, lo;
#pragma unroll
            for (int q = 0; q < 16; q++) {
                __nv_bfloat16 h = __float2bfloat16(f[q]);
                hi.b[q] = h;
                lo.b[q] = __float2bfloat16(f[q] - __bfloat162float(h));
            }
            char* pa = sA_hi + ld_row * PITCH + ld_half * 32;
            char* pl = sA_lo + ld_row * PITCH + ld_half * 32;
            *(uint4*)(pa)      = hi.u[0];
            *(uint4*)(pa + 16) = hi.u[1];
            *(uint4*)(pl)      = lo.u[0];
            *(uint4*)(pl + 16) = lo.u[1];
        }
        // ---- B: copy pre-split bf16 (K-major)
        {
            const uint4* bh = (const uint4*)(g_bhi + ld_row * KDIM + kc + ld_half * 16);
            const uint4* bl = (const uint4*)(g_blo + ld_row * KDIM + kc + ld_half * 16);
            char* ph = sB_hi + ld_row * PITCH + ld_half * 32;
            char* pl = sB_lo + ld_row * PITCH + ld_half * 32;
            *(uint4*)(ph)      = bh[0];
            *(uint4*)(ph + 16) = bh[1];
            *(uint4*)(pl)      = bl[0];
            *(uint4*)(pl + 16) = bl[1];
        }
        __syncthreads();

#pragma unroll
        for (int ks = 0; ks < 2; ks++) {
            const int k0 = ks * 16;
            uint32_t ah[2][4], al[2][4];
#pragma unroll
            for (int mg = 0; mg < 2; mg++) {
                int row = warpM * 32 + mg * 16 + a_roff;
                uint32_t off = (uint32_t)(row * PITCH + (k0 + a_koff) * 2);
                ldmatrix_x4(ah[mg][0], ah[mg][1], ah[mg][2], ah[mg][3], sAhi + off);
                ldmatrix_x4(al[mg][0], al[mg][1], al[mg][2], al[mg][3], sAlo + off);
            }
            uint32_t bh[4][4], bl[4][4];
#pragma unroll
            for (int g = 0; g < 4; g++) {
                int n = warpN * 64 + g * 16 + b_noff;
                uint32_t off = (uint32_t)(n * PITCH + (k0 + b_koff) * 2);
                ldmatrix_x4(bh[g][0], bh[g][1], bh[g][2], bh[g][3], sBhi + off);
                ldmatrix_x4(bl[g][0], bl[g][1], bl[g][2], bl[g][3], sBlo + off);
            }
#pragma unroll
            for (int mg = 0; mg < 2; mg++) {
#pragma unroll
                for (int ng = 0; ng < 8; ng++) {
                    int g = ng >> 1, s = (ng & 1) * 2;
                    mma_bf16(acc[mg][ng], ah[mg], bh[g][s], bh[g][s + 1]); // hi*hi
                    mma_bf16(acc[mg][ng], al[mg], bh[g][s], bh[g][s + 1]); // lo*hi
                    mma_bf16(acc[mg][ng], ah[mg], bl[g][s], bl[g][s + 1]); // hi*lo
                }
            }
        }
        __syncthreads();
    }

    // ---- epilogue: write h as fp16
    const int qrow = lane >> 2;          // 0..7
    const int qcol = (lane & 3) * 2;     // 0,2,4,6
#pragma unroll
    for (int mg = 0; mg < 2; mg++) {
#pragma unroll
        for (int ng = 0; ng < 8; ng++) {
            int col = warpN * 64 + ng * 8 + qcol;
            int r0 = block_row + warpM * 32 + mg * 16 + qrow;
            if (r0 < M)
                *(__half2*)(g_h + (size_t)r0 * UDIM + col) =
                    __floats2half2_rn(acc[mg][ng][0], acc[mg][ng][1]);
            int r1 = r0 + 8;
            if (r1 < M)
                *(__half2*)(g_h + (size_t)r1 * UDIM + col) =
                    __floats2half2_rn(acc[mg][ng][2], acc[mg][ng][3]);
        }
    }
}

// ============================================================================
// 2) CSR build: scan (3 phases) + scatter.  scan_final self-zeroes g_cnt.
// ============================================================================
__global__ __launch_bounds__(SCAN_TILE) void scan_bsum_kernel(int n)
{
    __shared__ int wsum[SCAN_TILE / 32];
    const int tid  = threadIdx.x;
    const int lane = tid & 31;
    const int wid  = tid >> 5;
    int i = blockIdx.x * SCAN_TILE + tid;
    int v = (i < n) ? g_cnt[i] : 0;

#pragma unroll
    for (int off = 16; off > 0; off >>= 1)
        v += __shfl_down_sync(0xffffffffu, v, off);
    if (lane == 0) wsum[wid] = v;
    __syncthreads();
    if (wid == 0) {
        int w = (lane < SCAN_TILE / 32) ? wsum[lane] : 0;
#pragma unroll
        for (int off = 16; off > 0; off >>= 1)
            w += __shfl_down_sync(0xffffffffu, w, off);
        if (lane == 0) g_bsum[blockIdx.x] = w;
    }
}

__global__ __launch_bounds__(1024) void scan_bases_kernel(int nb)
{
    __shared__ int wsum[32];
    const int tid  = threadIdx.x;
    const int lane = tid & 31;
    const int wid  = tid >> 5;
    int v = (tid < nb) ? g_bsum[tid] : 0;

    int s = v;
#pragma unroll
    for (int off = 1; off < 32; off <<= 1) {
        int t = __shfl_up_sync(0xffffffffu, s, off);
        if (lane >= off) s += t;
    }
    if (lane == 31) wsum[wid] = s;
    __syncthreads();
    if (wid == 0) {
        int w = wsum[lane];
#pragma unroll
        for (int off = 1; off < 32; off <<= 1) {
            int t = __shfl_up_sync(0xffffffffu, w, off);
            if (lane >= off) w += t;
        }
        wsum[lane] = w;
    }
    __syncthreads();
    int wp = (wid > 0) ? wsum[wid - 1] : 0;
    if (tid < nb) g_bsum[tid] = wp + s - v;
}

__global__ __launch_bounds__(SCAN_TILE) void scan_final_kernel(int n)
{
    __shared__ int wsum[SCAN_TILE / 32];
    const int tid  = threadIdx.x;
    const int lane = tid & 31;
    const int wid  = tid >> 5;
    int i = blockIdx.x * SCAN_TILE + tid;
    int v = (i < n) ? g_cnt[i] : 0;

    int s = v;
#pragma unroll
    for (int off = 1; off < 32; off <<= 1) {
        int t = __shfl_up_sync(0xffffffffu, s, off);
        if (lane >= off) s += t;
    }
    if (lane == 31) wsum[wid] = s;
    __syncthreads();
    if (wid == 0) {
        int w = wsum[lane];
#pragma unroll
        for (int off = 1; off < 32; off <<= 1) {
            int t = __shfl_up_sync(0xffffffffu, w, off);
            if (lane >= off) w += t;
        }
        wsum[lane] = w;
    }
    __syncthreads();
    int wp = (wid > 0) ? wsum[wid - 1] : 0;
    int incl = g_bsum[blockIdx.x] + wp + s;
    if (i < n) {
        g_off[i + 1] = incl;
        g_cur[i]     = incl - v;
        g_cnt[i]     = 0;        // self-zero for the next graph replay
    }
    if (i == 0) g_off[0] = 0;
}

__global__ void scatter_kernel(const int* __restrict__ rows,
                               const int* __restrict__ cols,
                               const float* __restrict__ vals, int E)
{
    int i = blockIdx.x * blockDim.x + threadIdx.x;
    if (i < E) {
        int r = rows[i];
        int p = atomicAdd(&g_cur[r], 1);
        unsigned long long packed =
            (unsigned long long)(unsigned)cols[i] |
            ((unsigned long long)__float_as_uint(vals[i]) << 32);
        g_cv[p] = packed;
    }
}

// ============================================================================
// 3) Segment reduce: one warp per output row, fp16 h gathers, fp32 accum
// ============================================================================
__global__ void reduce_kernel(float* __restrict__ out, int M)
{
    int warp = (blockIdx.x * blockDim.x + threadIdx.x) >> 5;
    int lane = threadIdx.x & 31;
    if (warp >= M) return;

    int s = g_off[warp];
    int e = g_off[warp + 1];

    float4 acc = make_float4(0.f, 0.f, 0.f, 0.f);
    int i = s;
    for (; i + 3 < e; i += 4) {
        unsigned long long p0 = __ldg(&g_cv[i]);
        unsigned long long p1 = __ldg(&g_cv[i + 1]);
        unsigned long long p2 = __ldg(&g_cv[i + 2]);
        unsigned long long p3 = __ldg(&g_cv[i + 3]);
        int c0 = (int)(unsigned)(p0 & 0xffffffffu);
        int c1 = (int)(unsigned)(p1 & 0xffffffffu);
        int c2 = (int)(unsigned)(p2 & 0xffffffffu);
        int c3 = (int)(unsigned)(p3 & 0xffffffffu);
        float v0 = __uint_as_float((unsigned)(p0 >> 32));
        float v1 = __uint_as_float((unsigned)(p1 >> 32));
        float v2 = __uint_as_float((unsigned)(p2 >> 32));
        float v3 = __uint_as_float((unsigned)(p3 >> 32));
        uint2 u0 = ((const uint2*)(g_h + (size_t)c0 * UDIM))[lane];
        uint2 u1 = ((const uint2*)(g_h + (size_t)c1 * UDIM))[lane];
        uint2 u2 = ((const uint2*)(g_h + (size_t)c2 * UDIM))[lane];
        uint2 u3 = ((const uint2*)(g_h + (size_t)c3 * UDIM))[lane];
        float2 a0 = __half22float2(*(__half2*)&u0.x);
        float2 b0 = __half22float2(*(__half2*)&u0.y);
        float2 a1 = __half22float2(*(__half2*)&u1.x);
        float2 b1 = __half22float2(*(__half2*)&u1.y);
        float2 a2 = __half22float2(*(__half2*)&u2.x);
        float2 b2 = __half22float2(*(__half2*)&u2.y);
        float2 a3 = __half22float2(*(__half2*)&u3.x);
        float2 b3 = __half22float2(*(__half2*)&u3.y);
        acc.x = fmaf(v0, a0.x, acc.x); acc.y = fmaf(v0, a0.y, acc.y);
        acc.z = fmaf(v0, b0.x, acc.z); acc.w = fmaf(v0, b0.y, acc.w);
        acc.x = fmaf(v1, a1.x, acc.x); acc.y = fmaf(v1, a1.y, acc.y);
        acc.z = fmaf(v1, b1.x, acc.z); acc.w = fmaf(v1, b1.y, acc.w);
        acc.x = fmaf(v2, a2.x, acc.x); acc.y = fmaf(v2, a2.y, acc.y);
        acc.z = fmaf(v2, b2.x, acc.z); acc.w = fmaf(v2, b2.y, acc.w);
        acc.x = fmaf(v3, a3.x, acc.x); acc.y = fmaf(v3, a3.y, acc.y);
        acc.z = fmaf(v3, b3.x, acc.z); acc.w = fmaf(v3, b3.y, acc.w);
    }
    for (; i < e; i++) {
        unsigned long long p0 = __ldg(&g_cv[i]);
        int c0 = (int)(unsigned)(p0 & 0xffffffffu);
        float v0 = __uint_as_float((unsigned)(p0 >> 32));
        uint2 u0 = ((const uint2*)(g_h + (size_t)c0 * UDIM))[lane];
        float2 a0 = __half22float2(*(__half2*)&u0.x);
        float2 b0 = __half22float2(*(__half2*)&u0.y);
        acc.x = fmaf(v0, a0.x, acc.x); acc.y = fmaf(v0, a0.y, acc.y);
        acc.z = fmaf(v0, b0.x, acc.z); acc.w = fmaf(v0, b0.y, acc.w);
    }

    acc.x = fmaxf(acc.x, 0.f); acc.y = fmaxf(acc.y, 0.f);
    acc.z = fmaxf(acc.z, 0.f); acc.w = fmaxf(acc.w, 0.f);

    ((float4*)(out + (size_t)warp * UDIM))[lane] = acc;
}

// ============================================================================
// launch
// ============================================================================
extern "C" void kernel_launch(void* const* d_in, const int* in_sizes, int n_in,
                              void* d_out, int out_size)
{
    const float* x      = (const float*)d_in[0];  // [M, 256]
    const float* kernel = (const float*)d_in[1];  // [256, 128]
    const int*   arows  = (const int*)d_in[2];    // [E]
    const int*   acols  = (const int*)d_in[3];    // [E]
    const float* avals  = (const float*)d_in[4];  // [E]
    float*       out    = (float*)d_out;          // [M, 128]

    const int M = in_sizes[0] / KDIM;
    const int E = in_sizes[2];
    const int nb = (M + SCAN_TILE - 1) / SCAN_TILE;

    const int gemm_nb = (M + 127) / 128;

    // 1) W prep, then FUSED hist-first + GEMM (hist grid-stride, 2 blocks/SM)
    wprep_kernel<<<(KDIM * UDIM + 255) / 256, 256>>>(kernel);
    gemm_hist_kernel<<<HIST_BLKS + gemm_nb, 256>>>(x, arows, M, E);

    // 2) scan + scatter (scan_final self-zeroes g_cnt for the next replay)
    scan_bsum_kernel<<<nb, SCAN_TILE>>>(M);
    scan_bases_kernel<<<1, 1024>>>(nb);
    scan_final_kernel<<<nb, SCAN_TILE>>>(M);
    scatter_kernel<<<(E + 255) / 256, 256>>>(arows, acols, avals, E);

    // 3) atomic-free segment reduce + relu (fp16 gathers)
    int warps_per_block = 256 / 32;
    int blocks = (M + warps_per_block - 1) / warps_per_block;
    reduce_kernel<<<blocks, 256>>>(out, M);
}

// round 9
// speedup vs baseline: 1.3545x; 1.2054x over previous
#include <cuda_runtime.h>
#include <cuda_bf16.h>
#include <cuda_fp16.h>
#include <cstdint>

// Problem constants (fixed by the dataset)
#define KDIM 256      // IN_DIM
#define UDIM 128      // UNITS
#define MAX_NODES 100000
#define MAX_EDGES 3200000

// ---------------- device scratch (static globals: no runtime alloc) ----------
__device__ __half             g_h[(size_t)MAX_NODES * UDIM];   // 25.6 MB (fp16)
__device__ int                g_cnt[MAX_NODES];                // zero-init; self-zeroing
__device__ int                g_off[MAX_NODES + 1];
__device__ int                g_cur[MAX_NODES];
__device__ int                g_bsum[256];
__device__ unsigned long long g_cv[MAX_EDGES];                 // packed (col, val)
__device__ int                g_bar[4];                        // barrier counters (self-reset)
__device__ int                g_dep[4];                        // depart counters (self-reset)

#define CSR_BLKS 96

// ---------------- small helpers ----------------------------------------------
__device__ __forceinline__ uint32_t smem_u32(const void* p) {
    uint32_t a;
    asm("{ .reg .u64 t; cvta.to.shared.u64 t, %1; cvt.u32.u64 %0, t; }"
        : "=r"(a) : "l"(p));
    return a;
}

__device__ __forceinline__ void ldmatrix_x4(uint32_t& r0, uint32_t& r1,
                                            uint32_t& r2, uint32_t& r3,
                                            uint32_t addr)
{
    asm volatile("ldmatrix.sync.aligned.m8n8.x4.shared.b16 {%0,%1,%2,%3}, [%4];"
                 : "=r"(r0), "=r"(r1), "=r"(r2), "=r"(r3) : "r"(addr));
}

__device__ __forceinline__ void mma_bf16(float* d, const uint32_t* a,
                                         uint32_t b0, uint32_t b1)
{
    asm volatile(
        "mma.sync.aligned.m16n8k16.row.col.f32.bf16.bf16.f32 "
        "{%0,%1,%2,%3}, {%4,%5,%6,%7}, {%8,%9}, {%0,%1,%2,%3};"
        : "+f"(d[0]), "+f"(d[1]), "+f"(d[2]), "+f"(d[3])
        : "r"(a[0]), "r"(a[1]), "r"(a[2]), "r"(a[3]), "r"(b0), "r"(b1));
}

// Inter-block barrier among the CSR blocks only (all co-resident: 96 <= 148
// SMs even at 1 CTA/SM). Counter + depart-count; last departer resets both,
// so state returns to zero for the next graph replay.
__device__ __forceinline__ void csr_barrier(int k, int N)
{
    __threadfence();            // publish this block's writes (all threads)
    __syncthreads();
    if (threadIdx.x == 0) {
        atomicAdd(&g_bar[k], 1);
        while (true) {
            int v;
            asm volatile("ld.acquire.gpu.b32 %0, [%1];"
                         : "=r"(v) : "l"(&g_bar[k]) : "memory");
            if (v >= N) break;
            __nanosleep(128);
        }
        int d = atomicAdd(&g_dep[k], 1);
        if (d == N - 1) {       // everyone has observed the release
            atomicExch(&g_dep[k], 0);
            atomicExch(&g_bar[k], 0);
        }
    }
    __syncthreads();
}

// ============================================================================
// FUSED kernel:
//   blocks [0, CSR_BLKS):          hist -> bar -> scan -> bar -> scatter
//   blocks [CSR_BLKS, +gemm_nb):   GEMM h = x@W (mma.sync bf16 hi/lo split)
// ============================================================================
#define PITCH 80

__global__ __launch_bounds__(256) void fused_kernel(
    const float* __restrict__ X, const float* __restrict__ W,
    const int* __restrict__ rows, const int* __restrict__ cols,
    const float* __restrict__ vals, int M, int E)
{
    __shared__ __align__(16) char sA_hi[128 * PITCH];
    __shared__ __align__(16) char sA_lo[128 * PITCH];
    __shared__ __align__(16) char sB_hi[128 * PITCH];
    __shared__ __align__(16) char sB_lo[128 * PITCH];
    __shared__ int wsum[8];

    const int tid = threadIdx.x;

    if ((int)blockIdx.x < CSR_BLKS) {
        // ================= CSR role =================
        const int bid    = blockIdx.x;
        const int stride = CSR_BLKS * 256;

        // ---- phase 1: histogram (grid-stride)
        for (int i = bid * 256 + tid; i < E; i += stride)
            atomicAdd(&g_cnt[rows[i]], 1);

        csr_barrier(0, CSR_BLKS);

        // ---- phase 2: distributed exclusive scan of g_cnt
        const int C   = (M + CSR_BLKS - 1) / CSR_BLKS;   // elems per block
        const int IPT = (C + 255) >> 8;                  // elems per thread (<=8)
        const int bstart = bid * C;
        const int bend   = min(bstart + C, M);
        const int i0     = bstart + tid * IPT;

        int loc[8];
        int s = 0;
#pragma unroll 8
        for (int j = 0; j < 8; j++) {
            int i = i0 + j;
            int v = (j < IPT && i < bend) ? g_cnt[i] : 0;
            loc[j] = v;
            s += v;
        }
        // block scan of 256 thread sums
        const int lane = tid & 31, w = tid >> 5;
        int p = s;
#pragma unroll
        for (int off = 1; off < 32; off <<= 1) {
            int t2 = __shfl_up_sync(0xffffffffu, p, off);
            if (lane >= off) p += t2;
        }
        if (lane == 31) wsum[w] = p;
        __syncthreads();
        if (w == 0) {
            int q = (lane < 8) ? wsum[lane] : 0;
#pragma unroll
            for (int off = 1; off < 8; off <<= 1) {
                int t2 = __shfl_up_sync(0xffffffffu, q, off);
                if (lane >= off) q += t2;
            }
            if (lane < 8) wsum[lane] = q;
        }
        __syncthreads();
        int excl  = (p - s) + ((w > 0) ? wsum[w - 1] : 0);
        int total = wsum[7];
        if (tid == 0) g_bsum[bid] = total;

        csr_barrier(1, CSR_BLKS);

        // block base = sum of totals of blocks < bid
        int* red = (int*)sA_hi;
        int v = (tid < bid) ? g_bsum[tid] : 0;   // bid <= 95 < 256
        red[tid] = v;
        __syncthreads();
#pragma unroll
        for (int st = 128; st > 0; st >>= 1) {
            if (tid < st) red[tid] += red[tid + st];
            __syncthreads();
        }
        int run = red[0] + excl;

        // write g_off (inclusive at i+1), g_cur (exclusive), self-zero g_cnt
#pragma unroll 8
        for (int j = 0; j < 8; j++) {
            int i = i0 + j;
            if (j < IPT && i < bend) {
                run += loc[j];
                g_off[i + 1] = run;
                g_cur[i]     = run - loc[j];
                g_cnt[i]     = 0;
            }
        }
        if (bid == 0 && tid == 0) g_off[0] = 0;

        csr_barrier(2, CSR_BLKS);

        // ---- phase 3: scatter (grid-stride)
        for (int i = bid * 256 + tid; i < E; i += stride) {
            int r = rows[i];
            int ppos = atomicAdd(&g_cur[r], 1);
            unsigned long long packed =
                (unsigned long long)(unsigned)cols[i] |
                ((unsigned long long)__float_as_uint(vals[i]) << 32);
            g_cv[ppos] = packed;
        }
        return;
    }

    // ================= GEMM role =================
    const int wid  = tid >> 5;
    const int lane = tid & 31;
    const int warpM = wid & 3;        // 4 groups of 32 rows
    const int warpN = wid >> 2;       // 2 groups of 64 cols
    const int block_row = (blockIdx.x - CSR_BLKS) * 128;

    float acc[2][8][4];
#pragma unroll
    for (int mg = 0; mg < 2; mg++)
#pragma unroll
        for (int ng = 0; ng < 8; ng++)
#pragma unroll
            for (int q = 0; q < 4; q++) acc[mg][ng][q] = 0.0f;

    const int matIdx = lane >> 3;
    const int rowInMat = lane & 7;
    const int a_roff = rowInMat + (matIdx & 1) * 8;
    const int a_koff = (matIdx >> 1) * 8;
    const int b_noff = (matIdx >> 1) * 8 + rowInMat;
    const int b_koff = (matIdx & 1) * 8;

    const uint32_t sAhi = smem_u32(sA_hi);
    const uint32_t sAlo = smem_u32(sA_lo);
    const uint32_t sBhi = smem_u32(sB_hi);
    const uint32_t sBlo = smem_u32(sB_lo);

    const int ld_row  = tid >> 1;     // 0..127
    const int ld_half = tid & 1;      // 0/1 -> 16 elements each
    // B loader mapping: one n-column, 16 k's
    const int b_n  = tid >> 1;        // 0..127
    const int b_k0 = (tid & 1) * 16;  // 0/16

#pragma unroll 1
    for (int kc = 0; kc < KDIM; kc += 32) {
        // ---- A: load 16 fp32, split hi/lo, store bf16
        {
            int grow = block_row + ld_row;
            float f[16];
            if (grow < M) {
                const float4* xp = (const float4*)(X + (size_t)grow * KDIM + kc + ld_half * 16);
#pragma unroll
                for (int q = 0; q < 4; q++) {
                    float4 v = xp[q];
                    f[q * 4 + 0] = v.x; f[q * 4 + 1] = v.y;
                    f[q * 4 + 2] = v.z; f[q * 4 + 3] = v.w;
                }
            } else {
#pragma unroll
                for (int q = 0; q < 16; q++) f[q] = 0.0f;
            }
            union { __nv_bfloat16 b[16]; uint4 u[2]; } hi, lo;
#pragma unroll
            for (int q = 0; q < 16; q++) {
                __nv_bfloat16 h = __float2bfloat16(f[q]);
                hi.b[q] = h;
                lo.b[q] = __float2bfloat16(f[q] - __bfloat162float(h));
            }
            char* pa = sA_hi + ld_row * PITCH + ld_half * 32;
            char* pl = sA_lo + ld_row * PITCH + ld_half * 32;
            *(uint4*)(pa)      = hi.u[0];
            *(uint4*)(pa + 16) = hi.u[1];
            *(uint4*)(pl)      = lo.u[0];
            *(uint4*)(pl + 16) = lo.u[1];
        }
        // ---- B: load W fp32 chunk, split hi/lo + transpose to K-major
        {
            union { __nv_bfloat16 b[16]; uint4 u[2]; } hi, lo;
#pragma unroll
            for (int j = 0; j < 16; j++) {
                float wv = W[(size_t)(kc + b_k0 + j) * UDIM + b_n];
                __nv_bfloat16 h = __float2bfloat16(wv);
                hi.b[j] = h;
                lo.b[j] = __float2bfloat16(wv - __bfloat162float(h));
            }
            char* ph = sB_hi + b_n * PITCH + b_k0 * 2;
            char* pl = sB_lo + b_n * PITCH + b_k0 * 2;
            *(uint4*)(ph)      = hi.u[0];
            *(uint4*)(ph + 16) = hi.u[1];
            *(uint4*)(pl)      = lo.u[0];
            *(uint4*)(pl + 16) = lo.u[1];
        }
        __syncthreads();

#pragma unroll
        for (int ks = 0; ks < 2; ks++) {
            const int k0 = ks * 16;
            uint32_t ah[2][4], al[2][4];
#pragma unroll
            for (int mg = 0; mg < 2; mg++) {
                int row = warpM * 32 + mg * 16 + a_roff;
                uint32_t off = (uint32_t)(row * PITCH + (k0 + a_koff) * 2);
                ldmatrix_x4(ah[mg][0], ah[mg][1], ah[mg][2], ah[mg][3], sAhi + off);
                ldmatrix_x4(al[mg][0], al[mg][1], al[mg][2], al[mg][3], sAlo + off);
            }
            uint32_t bh[4][4], bl[4][4];
#pragma unroll
            for (int g = 0; g < 4; g++) {
                int n = warpN * 64 + g * 16 + b_noff;
                uint32_t off = (uint32_t)(n * PITCH + (k0 + b_koff) * 2);
                ldmatrix_x4(bh[g][0], bh[g][1], bh[g][2], bh[g][3], sBhi + off);
                ldmatrix_x4(bl[g][0], bl[g][1], bl[g][2], bl[g][3], sBlo + off);
            }
#pragma unroll
            for (int mg = 0; mg < 2; mg++) {
#pragma unroll
                for (int ng = 0; ng < 8; ng++) {
                    int g = ng >> 1, sgl = (ng & 1) * 2;
                    mma_bf16(acc[mg][ng], ah[mg], bh[g][sgl], bh[g][sgl + 1]); // hi*hi
                    mma_bf16(acc[mg][ng], al[mg], bh[g][sgl], bh[g][sgl + 1]); // lo*hi
                    mma_bf16(acc[mg][ng], ah[mg], bl[g][sgl], bl[g][sgl + 1]); // hi*lo
                }
            }
        }
        __syncthreads();
    }

    // ---- epilogue: write h as fp16
    const int qrow = lane >> 2;          // 0..7
    const int qcol = (lane & 3) * 2;     // 0,2,4,6
#pragma unroll
    for (int mg = 0; mg < 2; mg++) {
#pragma unroll
        for (int ng = 0; ng < 8; ng++) {
            int col = warpN * 64 + ng * 8 + qcol;
            int r0 = block_row + warpM * 32 + mg * 16 + qrow;
            if (r0 < M)
                *(__half2*)(g_h + (size_t)r0 * UDIM + col) =
                    __floats2half2_rn(acc[mg][ng][0], acc[mg][ng][1]);
            int r1 = r0 + 8;
            if (r1 < M)
                *(__half2*)(g_h + (size_t)r1 * UDIM + col) =
                    __floats2half2_rn(acc[mg][ng][2], acc[mg][ng][3]);
        }
    }
}

// ============================================================================
// Segment reduce: one warp per output row, fp16 h gathers, fp32 accum
// ============================================================================
__global__ void reduce_kernel(float* __restrict__ out, int M)
{
    int warp = (blockIdx.x * blockDim.x + threadIdx.x) >> 5;
    int lane = threadIdx.x & 31;
    if (warp >= M) return;

    int s = g_off[warp];
    int e = g_off[warp + 1];

    float4 acc = make_float4(0.f, 0.f, 0.f, 0.f);
    int i = s;
    for (; i + 3 < e; i += 4) {
        unsigned long long p0 = __ldg(&g_cv[i]);
        unsigned long long p1 = __ldg(&g_cv[i + 1]);
        unsigned long long p2 = __ldg(&g_cv[i + 2]);
        unsigned long long p3 = __ldg(&g_cv[i + 3]);
        int c0 = (int)(unsigned)(p0 & 0xffffffffu);
        int c1 = (int)(unsigned)(p1 & 0xffffffffu);
        int c2 = (int)(unsigned)(p2 & 0xffffffffu);
        int c3 = (int)(unsigned)(p3 & 0xffffffffu);
        float v0 = __uint_as_float((unsigned)(p0 >> 32));
        float v1 = __uint_as_float((unsigned)(p1 >> 32));
        float v2 = __uint_as_float((unsigned)(p2 >> 32));
        float v3 = __uint_as_float((unsigned)(p3 >> 32));
        uint2 u0 = ((const uint2*)(g_h + (size_t)c0 * UDIM))[lane];
        uint2 u1 = ((const uint2*)(g_h + (size_t)c1 * UDIM))[lane];
        uint2 u2 = ((const uint2*)(g_h + (size_t)c2 * UDIM))[lane];
        uint2 u3 = ((const uint2*)(g_h + (size_t)c3 * UDIM))[lane];
        float2 a0 = __half22float2(*(__half2*)&u0.x);
        float2 b0 = __half22float2(*(__half2*)&u0.y);
        float2 a1 = __half22float2(*(__half2*)&u1.x);
        float2 b1 = __half22float2(*(__half2*)&u1.y);
        float2 a2 = __half22float2(*(__half2*)&u2.x);
        float2 b2 = __half22float2(*(__half2*)&u2.y);
        float2 a3 = __half22float2(*(__half2*)&u3.x);
        float2 b3 = __half22float2(*(__half2*)&u3.y);
        acc.x = fmaf(v0, a0.x, acc.x); acc.y = fmaf(v0, a0.y, acc.y);
        acc.z = fmaf(v0, b0.x, acc.z); acc.w = fmaf(v0, b0.y, acc.w);
        acc.x = fmaf(v1, a1.x, acc.x); acc.y = fmaf(v1, a1.y, acc.y);
        acc.z = fmaf(v1, b1.x, acc.z); acc.w = fmaf(v1, b1.y, acc.w);
        acc.x = fmaf(v2, a2.x, acc.x); acc.y = fmaf(v2, a2.y, acc.y);
        acc.z = fmaf(v2, b2.x, acc.z); acc.w = fmaf(v2, b2.y, acc.w);
        acc.x = fmaf(v3, a3.x, acc.x); acc.y = fmaf(v3, a3.y, acc.y);
        acc.z = fmaf(v3, b3.x, acc.z); acc.w = fmaf(v3, b3.y, acc.w);
    }
    for (; i < e; i++) {
        unsigned long long p0 = __ldg(&g_cv[i]);
        int c0 = (int)(unsigned)(p0 & 0xffffffffu);
        float v0 = __uint_as_float((unsigned)(p0 >> 32));
        uint2 u0 = ((const uint2*)(g_h + (size_t)c0 * UDIM))[lane];
        float2 a0 = __half22float2(*(__half2*)&u0.x);
        float2 b0 = __half22float2(*(__half2*)&u0.y);
        acc.x = fmaf(v0, a0.x, acc.x); acc.y = fmaf(v0, a0.y, acc.y);
        acc.z = fmaf(v0, b0.x, acc.z); acc.w = fmaf(v0, b0.y, acc.w);
    }

    acc.x = fmaxf(acc.x, 0.f); acc.y = fmaxf(acc.y, 0.f);
    acc.z = fmaxf(acc.z, 0.f); acc.w = fmaxf(acc.w, 0.f);

    ((float4*)(out + (size_t)warp * UDIM))[lane] = acc;
}

// ============================================================================
// launch
// ============================================================================
extern "C" void kernel_launch(void* const* d_in, const int* in_sizes, int n_in,
                              void* d_out, int out_size)
{
    const float* x      = (const float*)d_in[0];  // [M, 256]
    const float* kernel = (const float*)d_in[1];  // [256, 128]
    const int*   arows  = (const int*)d_in[2];    // [E]
    const int*   acols  = (const int*)d_in[3];    // [E]
    const float* avals  = (const float*)d_in[4];  // [E]
    float*       out    = (float*)d_out;          // [M, 128]

    const int M = in_sizes[0] / KDIM;
    const int E = in_sizes[2];
    const int gemm_nb = (M + 127) / 128;

    // 1) ONE fused kernel: CSR pipeline (hist->scan->scatter via inter-block
    //    barriers among 96 co-resident blocks) overlapped with the GEMM
    fused_kernel<<<CSR_BLKS + gemm_nb, 256>>>(x, kernel, arows, acols, avals, M, E);

    // 2) segment reduce + relu (fp16 gathers)
    reduce_kernel<<<(M * 32 + 255) / 256, 256>>>(out, M);
}